// round 1
// baseline (speedup 1.0000x reference)
#include <cuda_runtime.h>
#include <math_constants.h>

#define NUM_HEADS 32
#define NUM_KV    8
#define HEAD_DIM  128
#define HIDDEN    4096
#define BSZ       32
#define MAX_SEQ   4096
#define GROUP     4                          // NUM_HEADS / NUM_KV
#define QKV_OUT   ((NUM_HEADS + 2*NUM_KV)*HEAD_DIM)   // 6144
#define CHUNK     512
#define NCHUNK    (MAX_SEQ / CHUNK)          // 8
#define ATT_SCALE 0.08838834764831845f       // 128^-0.5

// ---------------- scratch (no allocs allowed) ----------------
__device__ float g_qkv [BSZ * QKV_OUT];                          // 786 KB
__device__ float g_attn[BSZ * NUM_HEADS * HEAD_DIM];             // 512 KB
__device__ float g_po  [BSZ * NUM_KV * GROUP * NCHUNK * HEAD_DIM]; // 4 MB
__device__ float g_pml [BSZ * NUM_KV * GROUP * NCHUNK * 2];

// ---------------------------------------------------------------
// GEMM: out[b*M + m] = sum_k x[b*K + k] * W[m*K + k] (+ bias[m])
// B = 32 fixed. Grid = M/32 blocks, 256 threads.
// ---------------------------------------------------------------
template<bool HAS_BIAS>
__global__ void __launch_bounds__(256)
gemm_xwT_kernel(const float* __restrict__ W, const float* __restrict__ x,
                const float* __restrict__ bias, float* __restrict__ out,
                int M, int K)
{
    const int BM = 32, BK = 64;
    __shared__ float Ws[BK][BM];
    __shared__ float xs[BK][BSZ];

    int m0 = blockIdx.x * BM;
    int t  = threadIdx.x;
    int ty = t >> 3;     // 0..31  -> row within tile
    int tx = t & 7;      // 0..7   -> batch cols tx*4 .. tx*4+3

    float acc[4] = {0.f, 0.f, 0.f, 0.f};

    for (int kk = 0; kk < K; kk += BK) {
        // W tile: 32 rows x 64 k = 512 float4
        #pragma unroll
        for (int i = 0; i < 2; i++) {
            int f  = t + i * 256;
            int r  = f >> 4;        // row 0..31
            int kv = f & 15;        // float4 index along k
            float4 w4 = *reinterpret_cast<const float4*>(
                &W[(size_t)(m0 + r) * K + kk + kv * 4]);
            Ws[kv*4+0][r] = w4.x; Ws[kv*4+1][r] = w4.y;
            Ws[kv*4+2][r] = w4.z; Ws[kv*4+3][r] = w4.w;
        }
        // x tile: 32 batches x 64 k
        #pragma unroll
        for (int i = 0; i < 2; i++) {
            int f  = t + i * 256;
            int b  = f >> 4;
            int kv = f & 15;
            float4 x4 = *reinterpret_cast<const float4*>(
                &x[(size_t)b * K + kk + kv * 4]);
            xs[kv*4+0][b] = x4.x; xs[kv*4+1][b] = x4.y;
            xs[kv*4+2][b] = x4.z; xs[kv*4+3][b] = x4.w;
        }
        __syncthreads();

        #pragma unroll
        for (int k = 0; k < BK; k++) {
            float a = Ws[k][ty];
            #pragma unroll
            for (int j = 0; j < 4; j++)
                acc[j] += a * xs[k][tx * 4 + j];
        }
        __syncthreads();
    }

    int m = m0 + ty;
    float bi = HAS_BIAS ? bias[m] : 0.f;
    #pragma unroll
    for (int j = 0; j < 4; j++)
        out[(size_t)(tx * 4 + j) * M + m] = acc[j] + bi;
}

// ---------------------------------------------------------------
// Flash-decode partial: grid (NCHUNK, NUM_KV, BSZ), 256 threads.
// Each warp strides tokens within the chunk; online softmax per warp;
// cross-warp LSE merge in smem; write chunk partial (m, l, o[128]).
// ---------------------------------------------------------------
__global__ void __launch_bounds__(256)
attn_partial_kernel(const float* __restrict__ kvc,
                    const int*   __restrict__ seq_lens,
                    const int*   __restrict__ slot_map)
{
    int b   = blockIdx.z;
    int kvh = blockIdx.y;
    int c   = blockIdx.x;

    int seq   = seq_lens[b];
    int start = c * CHUNK;
    if (start >= seq) return;
    int end  = min(seq, start + CHUNK);
    int slot = slot_map[b];

    int lane = threadIdx.x & 31;
    int warp = threadIdx.x >> 5;

    // q (4 grouped heads), pre-scaled; lane owns dims lane*4..lane*4+3
    float qr[GROUP][4];
    #pragma unroll
    for (int g = 0; g < GROUP; g++) {
        float4 q4 = *reinterpret_cast<const float4*>(
            &g_qkv[b * QKV_OUT + (kvh * GROUP + g) * HEAD_DIM + lane * 4]);
        qr[g][0] = q4.x * ATT_SCALE; qr[g][1] = q4.y * ATT_SCALE;
        qr[g][2] = q4.z * ATT_SCALE; qr[g][3] = q4.w * ATT_SCALE;
    }

    float m[GROUP], l[GROUP], o[GROUP][4];
    #pragma unroll
    for (int g = 0; g < GROUP; g++) {
        m[g] = -CUDART_INF_F; l[g] = 0.f;
        o[g][0] = o[g][1] = o[g][2] = o[g][3] = 0.f;
    }

    const size_t VPLANE = (size_t)BSZ * MAX_SEQ * NUM_KV * HEAD_DIM;
    const float* knew = &g_qkv[b * QKV_OUT + NUM_HEADS * HEAD_DIM            + kvh * HEAD_DIM];
    const float* vnew = &g_qkv[b * QKV_OUT + (NUM_HEADS + NUM_KV) * HEAD_DIM + kvh * HEAD_DIM];

    for (int s = start + warp; s < end; s += 8) {
        size_t base = (((size_t)b * MAX_SEQ + s) * NUM_KV + kvh) * HEAD_DIM + lane * 4;
        bool fresh = (s == slot);
        float4 k4 = fresh ? *reinterpret_cast<const float4*>(knew + lane * 4)
                          : *reinterpret_cast<const float4*>(&kvc[base]);
        float4 v4 = fresh ? *reinterpret_cast<const float4*>(vnew + lane * 4)
                          : *reinterpret_cast<const float4*>(&kvc[VPLANE + base]);

        float sc[GROUP];
        #pragma unroll
        for (int g = 0; g < GROUP; g++)
            sc[g] = qr[g][0]*k4.x + qr[g][1]*k4.y + qr[g][2]*k4.z + qr[g][3]*k4.w;

        #pragma unroll
        for (int off = 16; off >= 1; off >>= 1) {
            #pragma unroll
            for (int g = 0; g < GROUP; g++)
                sc[g] += __shfl_xor_sync(0xffffffffu, sc[g], off);
        }

        #pragma unroll
        for (int g = 0; g < GROUP; g++) {
            float mn   = fmaxf(m[g], sc[g]);
            float corr = __expf(m[g] - mn);     // exp(-inf - finite) = 0: safe
            float p    = __expf(sc[g] - mn);
            m[g] = mn;
            l[g] = l[g] * corr + p;
            o[g][0] = o[g][0] * corr + p * v4.x;
            o[g][1] = o[g][1] * corr + p * v4.y;
            o[g][2] = o[g][2] * corr + p * v4.z;
            o[g][3] = o[g][3] * corr + p * v4.w;
        }
    }

    // cross-warp merge
    __shared__ float sm_m[8][GROUP];
    __shared__ float sm_l[8][GROUP];
    __shared__ float sm_o[8][GROUP][HEAD_DIM];

    if (lane == 0) {
        #pragma unroll
        for (int g = 0; g < GROUP; g++) { sm_m[warp][g] = m[g]; sm_l[warp][g] = l[g]; }
    }
    #pragma unroll
    for (int g = 0; g < GROUP; g++) {
        sm_o[warp][g][lane*4+0] = o[g][0];
        sm_o[warp][g][lane*4+1] = o[g][1];
        sm_o[warp][g][lane*4+2] = o[g][2];
        sm_o[warp][g][lane*4+3] = o[g][3];
    }
    __syncthreads();

    if (warp < GROUP) {
        int g = warp;
        float M = -CUDART_INF_F;
        #pragma unroll
        for (int w = 0; w < 8; w++) M = fmaxf(M, sm_m[w][g]);
        float L = 0.f, O0 = 0.f, O1 = 0.f, O2 = 0.f, O3 = 0.f;
        #pragma unroll
        for (int w = 0; w < 8; w++) {
            float e = __expf(sm_m[w][g] - M);   // empty warps: exp(-inf - M) = 0
            L  += sm_l[w][g] * e;
            O0 += sm_o[w][g][lane*4+0] * e;
            O1 += sm_o[w][g][lane*4+1] * e;
            O2 += sm_o[w][g][lane*4+2] * e;
            O3 += sm_o[w][g][lane*4+3] * e;
        }
        size_t pidx = (((size_t)b * NUM_KV + kvh) * GROUP + g) * NCHUNK + c;
        *reinterpret_cast<float4*>(&g_po[pidx * HEAD_DIM + lane * 4]) =
            make_float4(O0, O1, O2, O3);
        if (lane == 0) { g_pml[pidx*2] = M; g_pml[pidx*2+1] = L; }
    }
}

// ---------------------------------------------------------------
// Chunk merge: grid (32 heads, 32 batches), 128 threads (one per dim)
// ---------------------------------------------------------------
__global__ void __launch_bounds__(128)
attn_reduce_kernel(const int* __restrict__ seq_lens)
{
    int h = blockIdx.x;         // 0..31 (q head)
    int b = blockIdx.y;         // 0..31
    int d = threadIdx.x;        // 0..127
    int seq = seq_lens[b];
    int nch = (seq + CHUNK - 1) / CHUNK;
    int kvh = h >> 2, g = h & 3;

    size_t base = (((size_t)b * NUM_KV + kvh) * GROUP + g) * NCHUNK;

    float M = -CUDART_INF_F;
    for (int cc = 0; cc < nch; cc++)
        M = fmaxf(M, g_pml[(base + cc) * 2]);
    float L = 0.f, O = 0.f;
    for (int cc = 0; cc < nch; cc++) {
        float e = __expf(g_pml[(base + cc) * 2] - M);
        L += g_pml[(base + cc) * 2 + 1] * e;
        O += g_po[(base + cc) * HEAD_DIM + d] * e;
    }
    g_attn[(size_t)b * HIDDEN + h * HEAD_DIM + d] = O / L;
}

// ---------------------------------------------------------------
extern "C" void kernel_launch(void* const* d_in, const int* in_sizes, int n_in,
                              void* d_out, int out_size)
{
    const float* hidden = (const float*)d_in[0];
    // d_in[1] = positions (unused: no RoPE in this module)
    const float* kvc    = (const float*)d_in[2];
    const int*   slot   = (const int*)  d_in[3];
    const int*   seql   = (const int*)  d_in[4];
    const float* Wqkv   = (const float*)d_in[5];
    const float* bqkv   = (const float*)d_in[6];
    const float* Wo     = (const float*)d_in[7];
    float*       out    = (float*)d_out;

    void *pq = nullptr, *pa = nullptr;
    cudaGetSymbolAddress(&pq, g_qkv);
    cudaGetSymbolAddress(&pa, g_attn);
    float* qkv  = (float*)pq;
    float* attn = (float*)pa;

    // 1) QKV projection: [32,6144]
    gemm_xwT_kernel<true><<<QKV_OUT / 32, 256>>>(Wqkv, hidden, bqkv, qkv, QKV_OUT, HIDDEN);

    // 2) flash-decode partials over sequence chunks
    attn_partial_kernel<<<dim3(NCHUNK, NUM_KV, BSZ), 256>>>(kvc, seql, slot);

    // 3) merge chunk partials -> attn [32, 4096]
    attn_reduce_kernel<<<dim3(NUM_HEADS, BSZ), 128>>>(seql);

    // 4) output projection -> d_out [32, 4096]
    gemm_xwT_kernel<false><<<HIDDEN / 32, 256>>>(Wo, attn, nullptr, out, HIDDEN, HIDDEN);
}

// round 2
// speedup vs baseline: 1.7937x; 1.7937x over previous
#include <cuda_runtime.h>
#include <math_constants.h>

#define NUM_HEADS 32
#define NUM_KV    8
#define HEAD_DIM  128
#define HIDDEN    4096
#define BSZ       32
#define MAX_SEQ   4096
#define GROUP     4
#define QKV_OUT   ((NUM_HEADS + 2*NUM_KV)*HEAD_DIM)   // 6144
#define CHUNK     256
#define NCHUNK    (MAX_SEQ / CHUNK)                   // 16
#define ATT_SCALE 0.08838834764831845f

// GEMM tiling
#define BM   128
#define BK   32
#define BMP  130      // padded smem stride (even -> 8B-aligned pairs)
#define SPLITK 8

// ---------------- scratch (no allocs allowed) ----------------
__device__ float g_qkv [BSZ * QKV_OUT];
__device__ float g_attn[BSZ * NUM_HEADS * HEAD_DIM];
__device__ float g_po  [BSZ * NUM_KV * GROUP * NCHUNK * HEAD_DIM];  // 8.4 MB
__device__ float g_pml [BSZ * NUM_KV * GROUP * NCHUNK * 2];

// packed fp32x2 FMA (Blackwell)
__device__ __forceinline__ void fma2(unsigned long long& d,
                                     unsigned long long a,
                                     unsigned long long b) {
    asm("fma.rn.f32x2 %0, %1, %2, %0;" : "+l"(d) : "l"(a), "l"(b));
}
__device__ __forceinline__ void unpack2(unsigned long long v, float& lo, float& hi) {
    asm("mov.b64 {%0,%1}, %2;" : "=f"(lo), "=f"(hi) : "l"(v));
}

// ---------------------------------------------------------------
// init: out[b*M + m] = bias[m] (or 0)
// ---------------------------------------------------------------
__global__ void __launch_bounds__(256)
init_bias_kernel(float* __restrict__ out, const float* __restrict__ bias, int M)
{
    int idx = blockIdx.x * 256 + threadIdx.x;
    if (idx >= BSZ * M) return;
    int m = idx % M;
    out[idx] = bias ? bias[m] : 0.f;
}

// ---------------------------------------------------------------
// Split-K GEMM: out[b*M+m] += sum_{k in my split} x[b,k]*W[m,k]
// grid (M/BM, SPLITK), 256 threads. FFMA2 packed math, double-buffered smem.
// ---------------------------------------------------------------
__global__ void __launch_bounds__(256)
gemm_splitk_kernel(const float* __restrict__ W, const float* __restrict__ x,
                   float* __restrict__ out, int M, int K)
{
    __shared__ __align__(16) float  Ws[2][BK][BMP];
    __shared__ __align__(16) float2 xs[2][BK][BSZ];   // duplicated (x,x) pairs

    const int m0     = blockIdx.x * BM;
    const int kspan  = K / SPLITK;                    // 512
    const int kbase  = blockIdx.y * kspan;
    const int ktiles = kspan / BK;                    // 16

    const int t  = threadIdx.x;
    const int ty = t >> 3;        // 0..31 -> rows m0+ty*4 .. +3
    const int tx = t & 7;         // batches tx*4 .. +3
    const int wrow = t >> 3;      // W-load row helper (f>>3 with i term added)
    const int wkv  = t & 7;

    float4 wreg[4];
    float4 xreg;

    // -------- prologue: load tile 0 --------
    {
        int kk = kbase;
        #pragma unroll
        for (int i = 0; i < 4; i++) {
            int f = t + i * 256;
            int r = f >> 3, kv = f & 7;
            wreg[i] = *reinterpret_cast<const float4*>(&W[(size_t)(m0 + r) * K + kk + kv * 4]);
        }
        int xb = t >> 3, xkv = t & 7;
        xreg = *reinterpret_cast<const float4*>(&x[(size_t)xb * K + kk + xkv * 4]);
        #pragma unroll
        for (int i = 0; i < 4; i++) {
            int f = t + i * 256;
            int r = f >> 3, kv = f & 7;
            Ws[0][kv*4+0][r] = wreg[i].x; Ws[0][kv*4+1][r] = wreg[i].y;
            Ws[0][kv*4+2][r] = wreg[i].z; Ws[0][kv*4+3][r] = wreg[i].w;
        }
        xs[0][xkv*4+0][xb] = make_float2(xreg.x, xreg.x);
        xs[0][xkv*4+1][xb] = make_float2(xreg.y, xreg.y);
        xs[0][xkv*4+2][xb] = make_float2(xreg.z, xreg.z);
        xs[0][xkv*4+3][xb] = make_float2(xreg.w, xreg.w);
    }
    __syncthreads();

    unsigned long long acc[2][4];
    #pragma unroll
    for (int rp = 0; rp < 2; rp++)
        #pragma unroll
        for (int j = 0; j < 4; j++) acc[rp][j] = 0ull;

    int p = 0;
    for (int tile = 0; tile < ktiles; tile++) {
        bool has_next = (tile + 1 < ktiles);
        if (has_next) {
            int kk = kbase + (tile + 1) * BK;
            #pragma unroll
            for (int i = 0; i < 4; i++) {
                int f = t + i * 256;
                int r = f >> 3, kv = f & 7;
                wreg[i] = *reinterpret_cast<const float4*>(&W[(size_t)(m0 + r) * K + kk + kv * 4]);
            }
            int xb = t >> 3, xkv = t & 7;
            xreg = *reinterpret_cast<const float4*>(&x[(size_t)xb * K + kk + xkv * 4]);
        }

        // -------- compute from buffer p --------
        #pragma unroll
        for (int k = 0; k < BK; k++) {
            unsigned long long w0 = *reinterpret_cast<const unsigned long long*>(&Ws[p][k][ty*4]);
            unsigned long long w1 = *reinterpret_cast<const unsigned long long*>(&Ws[p][k][ty*4+2]);
            const ulonglong2* xp = reinterpret_cast<const ulonglong2*>(&xs[p][k][tx*4]);
            ulonglong2 xv0 = xp[0];   // (b0,b0),(b1,b1)
            ulonglong2 xv1 = xp[1];   // (b2,b2),(b3,b3)
            fma2(acc[0][0], w0, xv0.x); fma2(acc[1][0], w1, xv0.x);
            fma2(acc[0][1], w0, xv0.y); fma2(acc[1][1], w1, xv0.y);
            fma2(acc[0][2], w0, xv1.x); fma2(acc[1][2], w1, xv1.x);
            fma2(acc[0][3], w0, xv1.y); fma2(acc[1][3], w1, xv1.y);
        }

        if (has_next) {
            int pn = p ^ 1;
            #pragma unroll
            for (int i = 0; i < 4; i++) {
                int f = t + i * 256;
                int r = f >> 3, kv = f & 7;
                Ws[pn][kv*4+0][r] = wreg[i].x; Ws[pn][kv*4+1][r] = wreg[i].y;
                Ws[pn][kv*4+2][r] = wreg[i].z; Ws[pn][kv*4+3][r] = wreg[i].w;
            }
            int xb = t >> 3, xkv = t & 7;
            xs[pn][xkv*4+0][xb] = make_float2(xreg.x, xreg.x);
            xs[pn][xkv*4+1][xb] = make_float2(xreg.y, xreg.y);
            xs[pn][xkv*4+2][xb] = make_float2(xreg.z, xreg.z);
            xs[pn][xkv*4+3][xb] = make_float2(xreg.w, xreg.w);
        }
        __syncthreads();
        p ^= 1;
    }

    // -------- epilogue: split-K accumulate --------
    #pragma unroll
    for (int rp = 0; rp < 2; rp++) {
        #pragma unroll
        for (int j = 0; j < 4; j++) {
            float lo, hi;
            unpack2(acc[rp][j], lo, hi);
            int b = tx * 4 + j;
            int m = m0 + ty * 4 + rp * 2;
            atomicAdd(&out[(size_t)b * M + m],     lo);
            atomicAdd(&out[(size_t)b * M + m + 1], hi);
        }
    }
}

// ---------------------------------------------------------------
// Flash-decode partial: grid (NCHUNK, NUM_KV, BSZ), 256 threads.
// Token-pair processing with next-pair prefetch for MLP.
// ---------------------------------------------------------------
__global__ void __launch_bounds__(256)
attn_partial_kernel(const float* __restrict__ kvc,
                    const int*   __restrict__ seq_lens,
                    const int*   __restrict__ slot_map)
{
    int b   = blockIdx.z;
    int kvh = blockIdx.y;
    int c   = blockIdx.x;

    int seq   = seq_lens[b];
    int start = c * CHUNK;
    if (start >= seq) return;
    int end  = min(seq, start + CHUNK);
    int slot = slot_map[b];

    int lane = threadIdx.x & 31;
    int warp = threadIdx.x >> 5;

    float qr[GROUP][4];
    #pragma unroll
    for (int g = 0; g < GROUP; g++) {
        float4 q4 = *reinterpret_cast<const float4*>(
            &g_qkv[b * QKV_OUT + (kvh * GROUP + g) * HEAD_DIM + lane * 4]);
        qr[g][0] = q4.x * ATT_SCALE; qr[g][1] = q4.y * ATT_SCALE;
        qr[g][2] = q4.z * ATT_SCALE; qr[g][3] = q4.w * ATT_SCALE;
    }

    float m[GROUP], l[GROUP], o[GROUP][4];
    #pragma unroll
    for (int g = 0; g < GROUP; g++) {
        m[g] = -CUDART_INF_F; l[g] = 0.f;
        o[g][0] = o[g][1] = o[g][2] = o[g][3] = 0.f;
    }

    const size_t VPLANE = (size_t)BSZ * MAX_SEQ * NUM_KV * HEAD_DIM;
    const float* knew = &g_qkv[b * QKV_OUT + NUM_HEADS * HEAD_DIM            + kvh * HEAD_DIM];
    const float* vnew = &g_qkv[b * QKV_OUT + (NUM_HEADS + NUM_KV) * HEAD_DIM + kvh * HEAD_DIM];

    auto ldkv = [&](int s, float4& kk, float4& vv) {
        size_t base = (((size_t)b * MAX_SEQ + s) * NUM_KV + kvh) * HEAD_DIM + lane * 4;
        if (s == slot) {
            kk = *reinterpret_cast<const float4*>(knew + lane * 4);
            vv = *reinterpret_cast<const float4*>(vnew + lane * 4);
        } else {
            kk = *reinterpret_cast<const float4*>(&kvc[base]);
            vv = *reinterpret_cast<const float4*>(&kvc[VPLANE + base]);
        }
    };

    int s = start + warp;
    if (s < end) {
        float4 ka, va, kb = make_float4(0,0,0,0), vb = make_float4(0,0,0,0);
        ldkv(s, ka, va);
        bool hb = (s + 8 < end);
        if (hb) ldkv(s + 8, kb, vb);

        for (;;) {
            int sn = s + 16;
            bool hna = sn < end, hnb = sn + 8 < end;
            float4 kna, vna, knb, vnb;
            if (hna) ldkv(sn, kna, vna);
            if (hnb) ldkv(sn + 8, knb, vnb);

            float sa[GROUP], sb[GROUP];
            #pragma unroll
            for (int g = 0; g < GROUP; g++) {
                sa[g] = qr[g][0]*ka.x + qr[g][1]*ka.y + qr[g][2]*ka.z + qr[g][3]*ka.w;
                sb[g] = qr[g][0]*kb.x + qr[g][1]*kb.y + qr[g][2]*kb.z + qr[g][3]*kb.w;
            }
            #pragma unroll
            for (int off = 16; off >= 1; off >>= 1) {
                #pragma unroll
                for (int g = 0; g < GROUP; g++) {
                    sa[g] += __shfl_xor_sync(0xffffffffu, sa[g], off);
                    sb[g] += __shfl_xor_sync(0xffffffffu, sb[g], off);
                }
            }
            #pragma unroll
            for (int g = 0; g < GROUP; g++) {
                // token A (always valid)
                float mn   = fmaxf(m[g], sa[g]);
                float corr = __expf(m[g] - mn);
                float pa   = __expf(sa[g] - mn);
                m[g] = mn;
                l[g] = l[g] * corr + pa;
                o[g][0] = o[g][0]*corr + pa*va.x;
                o[g][1] = o[g][1]*corr + pa*va.y;
                o[g][2] = o[g][2]*corr + pa*va.z;
                o[g][3] = o[g][3]*corr + pa*va.w;
                // token B
                float scb = hb ? sb[g] : -CUDART_INF_F;
                float mn2   = fmaxf(m[g], scb);
                float corr2 = __expf(m[g] - mn2);
                float pb    = __expf(scb - mn2);
                m[g] = mn2;
                l[g] = l[g] * corr2 + pb;
                o[g][0] = o[g][0]*corr2 + pb*vb.x;
                o[g][1] = o[g][1]*corr2 + pb*vb.y;
                o[g][2] = o[g][2]*corr2 + pb*vb.z;
                o[g][3] = o[g][3]*corr2 + pb*vb.w;
            }

            if (!hna) break;
            ka = kna; va = vna; kb = knb; vb = vnb; hb = hnb; s = sn;
        }
    }

    // cross-warp merge
    __shared__ float sm_m[8][GROUP];
    __shared__ float sm_l[8][GROUP];
    __shared__ float sm_o[8][GROUP][HEAD_DIM];

    if (lane == 0) {
        #pragma unroll
        for (int g = 0; g < GROUP; g++) { sm_m[warp][g] = m[g]; sm_l[warp][g] = l[g]; }
    }
    #pragma unroll
    for (int g = 0; g < GROUP; g++) {
        sm_o[warp][g][lane*4+0] = o[g][0];
        sm_o[warp][g][lane*4+1] = o[g][1];
        sm_o[warp][g][lane*4+2] = o[g][2];
        sm_o[warp][g][lane*4+3] = o[g][3];
    }
    __syncthreads();

    if (warp < GROUP) {
        int g = warp;
        float M = -CUDART_INF_F;
        #pragma unroll
        for (int w = 0; w < 8; w++) M = fmaxf(M, sm_m[w][g]);
        float L = 0.f, O0 = 0.f, O1 = 0.f, O2 = 0.f, O3 = 0.f;
        #pragma unroll
        for (int w = 0; w < 8; w++) {
            float e = __expf(sm_m[w][g] - M);
            L  += sm_l[w][g] * e;
            O0 += sm_o[w][g][lane*4+0] * e;
            O1 += sm_o[w][g][lane*4+1] * e;
            O2 += sm_o[w][g][lane*4+2] * e;
            O3 += sm_o[w][g][lane*4+3] * e;
        }
        size_t pidx = (((size_t)b * NUM_KV + kvh) * GROUP + g) * NCHUNK + c;
        *reinterpret_cast<float4*>(&g_po[pidx * HEAD_DIM + lane * 4]) =
            make_float4(O0, O1, O2, O3);
        if (lane == 0) { g_pml[pidx*2] = M; g_pml[pidx*2+1] = L; }
    }
}

// ---------------------------------------------------------------
// Chunk merge: grid (32 heads, 32 batches), 128 threads
// ---------------------------------------------------------------
__global__ void __launch_bounds__(128)
attn_reduce_kernel(const int* __restrict__ seq_lens)
{
    int h = blockIdx.x;
    int b = blockIdx.y;
    int d = threadIdx.x;
    int seq = seq_lens[b];
    int nch = (seq + CHUNK - 1) / CHUNK;
    int kvh = h >> 2, g = h & 3;

    size_t base = (((size_t)b * NUM_KV + kvh) * GROUP + g) * NCHUNK;

    float M = -CUDART_INF_F;
    for (int cc = 0; cc < nch; cc++)
        M = fmaxf(M, g_pml[(base + cc) * 2]);
    float L = 0.f, O = 0.f;
    for (int cc = 0; cc < nch; cc++) {
        float e = __expf(g_pml[(base + cc) * 2] - M);
        L += g_pml[(base + cc) * 2 + 1] * e;
        O += g_po[(base + cc) * HEAD_DIM + d] * e;
    }
    g_attn[(size_t)b * HIDDEN + h * HEAD_DIM + d] = O / L;
}

// ---------------------------------------------------------------
extern "C" void kernel_launch(void* const* d_in, const int* in_sizes, int n_in,
                              void* d_out, int out_size)
{
    const float* hidden = (const float*)d_in[0];
    const float* kvc    = (const float*)d_in[2];
    const int*   slot   = (const int*)  d_in[3];
    const int*   seql   = (const int*)  d_in[4];
    const float* Wqkv   = (const float*)d_in[5];
    const float* bqkv   = (const float*)d_in[6];
    const float* Wo     = (const float*)d_in[7];
    float*       out    = (float*)d_out;

    void *pq = nullptr, *pa = nullptr;
    cudaGetSymbolAddress(&pq, g_qkv);
    cudaGetSymbolAddress(&pa, g_attn);
    float* qkv  = (float*)pq;
    float* attn = (float*)pa;

    // init outputs (bias for qkv, zeros for out)
    init_bias_kernel<<<(BSZ * QKV_OUT + 255) / 256, 256>>>(qkv, bqkv, QKV_OUT);
    init_bias_kernel<<<(BSZ * HIDDEN + 255) / 256, 256>>>(out, nullptr, HIDDEN);

    // 1) QKV projection (split-K atomic)
    gemm_splitk_kernel<<<dim3(QKV_OUT / BM, SPLITK), 256>>>(Wqkv, hidden, qkv, QKV_OUT, HIDDEN);

    // 2) flash-decode partials
    attn_partial_kernel<<<dim3(NCHUNK, NUM_KV, BSZ), 256>>>(kvc, seql, slot);

    // 3) merge partials
    attn_reduce_kernel<<<dim3(NUM_HEADS, BSZ), 128>>>(seql);

    // 4) output projection (split-K atomic)
    gemm_splitk_kernel<<<dim3(HIDDEN / BM, SPLITK), 256>>>(Wo, attn, out, HIDDEN, HIDDEN);
}

// round 3
// speedup vs baseline: 2.7421x; 1.5288x over previous
#include <cuda_runtime.h>
#include <math_constants.h>

#define NUM_HEADS 32
#define NUM_KV    8
#define HEAD_DIM  128
#define HIDDEN    4096
#define BSZ       32
#define MAX_SEQ   4096
#define GROUP     4
#define QKV_OUT   6144
#define CHUNK     256
#define NCHUNK    16
// attention scale * log2(e): softmax done in exp2 domain
#define QSCALE    (0.08838834764831845f * 1.4426950408889634f)

// GEMM tiling: BM=512, BK=16, 256 threads, per-thread 8m x 8b
#define GBM 512
#define GBK 16
#define WST 516     // Ws row stride (floats): kills STS bank conflicts, keeps 16B align
#define XST 36      // Xs row stride
#define GSMEM ((2*GBK*WST + 2*GBK*XST) * 4)   // 70656 bytes

// ---------------- scratch (no allocs allowed) ----------------
__device__ float g_qkv [BSZ * QKV_OUT];
__device__ float g_attn[BSZ * NUM_HEADS * HEAD_DIM];
__device__ float g_po  [BSZ * NUM_KV * GROUP * NCHUNK * HEAD_DIM];
__device__ float g_pml [BSZ * NUM_KV * GROUP * NCHUNK * 2];

// packed fp32x2 FMA (Blackwell)
__device__ __forceinline__ void fma2(unsigned long long& d,
                                     unsigned long long a,
                                     unsigned long long b) {
    asm("fma.rn.f32x2 %0, %1, %2, %0;" : "+l"(d) : "l"(a), "l"(b));
}
__device__ __forceinline__ unsigned long long dup2(float v) {
    unsigned long long r;
    asm("mov.b64 %0, {%1, %1};" : "=l"(r) : "f"(v));
    return r;
}
__device__ __forceinline__ void unpack2(unsigned long long v, float& lo, float& hi) {
    asm("mov.b64 {%0,%1}, %2;" : "=f"(lo), "=f"(hi) : "l"(v));
}

// ---------------------------------------------------------------
__global__ void __launch_bounds__(256)
init_bias_kernel(float* __restrict__ out, const float* __restrict__ bias, int M)
{
    int idx = blockIdx.x * 256 + threadIdx.x;
    if (idx >= BSZ * M) return;
    out[idx] = bias ? bias[idx % M] : 0.f;
}

// ---------------------------------------------------------------
// Split-K GEMM, 8m x 8b register tiles, FFMA2, double-buffered smem.
// out[b*M+m] += sum_k x[b,k]*W[m,k]
// ---------------------------------------------------------------
__global__ void __launch_bounds__(256)
gemm8x8_kernel(const float* __restrict__ W, const float* __restrict__ x,
               float* __restrict__ out, int M, int K, int nsplit)
{
    extern __shared__ float sm[];
    float* Ws = sm;                       // [2][GBK][WST]
    float* Xs = sm + 2 * GBK * WST;       // [2][GBK][XST]

    const int m0    = blockIdx.x * GBM;
    const int tot   = K / GBK;
    const int tile0 = (blockIdx.y * tot) / nsplit;
    const int tile1 = ((blockIdx.y + 1) * tot) / nsplit;

    const int t  = threadIdx.x;
    const int ty = t >> 2;                // 0..63 -> 8 m rows
    const int tx = t & 3;                 // 0..3  -> 8 batches

    const int wr  = t >> 2;               // W load: base row (+64 per i)
    const int wkv = t & 3;                // float4 index within 16-k chunk
    const int xb  = t & 31;               // x load (threads<128): batch
    const int xkv = t >> 5;               // 0..3

    float4 wst[8];
    float4 xst;

    // ---- prologue ----
    {
        const float* wp = W + (size_t)(m0 + wr) * K + (size_t)tile0 * GBK + wkv * 4;
        #pragma unroll
        for (int i = 0; i < 8; i++)
            wst[i] = *reinterpret_cast<const float4*>(wp + (size_t)i * 64 * K);
        if (t < 128)
            xst = *reinterpret_cast<const float4*>(x + (size_t)xb * K + (size_t)tile0 * GBK + xkv * 4);

        #pragma unroll
        for (int i = 0; i < 8; i++) {
            int r = wr + i * 64;
            Ws[(wkv*4+0)*WST + r] = wst[i].x;
            Ws[(wkv*4+1)*WST + r] = wst[i].y;
            Ws[(wkv*4+2)*WST + r] = wst[i].z;
            Ws[(wkv*4+3)*WST + r] = wst[i].w;
        }
        if (t < 128) {
            Xs[(xkv*4+0)*XST + xb] = xst.x;
            Xs[(xkv*4+1)*XST + xb] = xst.y;
            Xs[(xkv*4+2)*XST + xb] = xst.z;
            Xs[(xkv*4+3)*XST + xb] = xst.w;
        }
    }
    __syncthreads();

    unsigned long long acc[4][8];
    #pragma unroll
    for (int i = 0; i < 4; i++)
        #pragma unroll
        for (int j = 0; j < 8; j++) acc[i][j] = 0ull;

    int p = 0;
    for (int tile = tile0; tile < tile1; tile++) {
        const bool has_next = (tile + 1 < tile1);
        if (has_next) {
            const float* wp = W + (size_t)(m0 + wr) * K + (size_t)(tile + 1) * GBK + wkv * 4;
            #pragma unroll
            for (int i = 0; i < 8; i++)
                wst[i] = *reinterpret_cast<const float4*>(wp + (size_t)i * 64 * K);
            if (t < 128)
                xst = *reinterpret_cast<const float4*>(x + (size_t)xb * K + (size_t)(tile + 1) * GBK + xkv * 4);
        }

        const float* wb = Ws + p * GBK * WST;
        const float* xbuf = Xs + p * GBK * XST;
        #pragma unroll
        for (int k = 0; k < GBK; k++) {
            ulonglong2 w01 = *reinterpret_cast<const ulonglong2*>(wb + k * WST + ty * 8);
            ulonglong2 w23 = *reinterpret_cast<const ulonglong2*>(wb + k * WST + ty * 8 + 4);
            float4 xa = *reinterpret_cast<const float4*>(xbuf + k * XST + tx * 8);
            float4 xc = *reinterpret_cast<const float4*>(xbuf + k * XST + tx * 8 + 4);
            unsigned long long xd;
            xd = dup2(xa.x);
            fma2(acc[0][0], w01.x, xd); fma2(acc[1][0], w01.y, xd);
            fma2(acc[2][0], w23.x, xd); fma2(acc[3][0], w23.y, xd);
            xd = dup2(xa.y);
            fma2(acc[0][1], w01.x, xd); fma2(acc[1][1], w01.y, xd);
            fma2(acc[2][1], w23.x, xd); fma2(acc[3][1], w23.y, xd);
            xd = dup2(xa.z);
            fma2(acc[0][2], w01.x, xd); fma2(acc[1][2], w01.y, xd);
            fma2(acc[2][2], w23.x, xd); fma2(acc[3][2], w23.y, xd);
            xd = dup2(xa.w);
            fma2(acc[0][3], w01.x, xd); fma2(acc[1][3], w01.y, xd);
            fma2(acc[2][3], w23.x, xd); fma2(acc[3][3], w23.y, xd);
            xd = dup2(xc.x);
            fma2(acc[0][4], w01.x, xd); fma2(acc[1][4], w01.y, xd);
            fma2(acc[2][4], w23.x, xd); fma2(acc[3][4], w23.y, xd);
            xd = dup2(xc.y);
            fma2(acc[0][5], w01.x, xd); fma2(acc[1][5], w01.y, xd);
            fma2(acc[2][5], w23.x, xd); fma2(acc[3][5], w23.y, xd);
            xd = dup2(xc.z);
            fma2(acc[0][6], w01.x, xd); fma2(acc[1][6], w01.y, xd);
            fma2(acc[2][6], w23.x, xd); fma2(acc[3][6], w23.y, xd);
            xd = dup2(xc.w);
            fma2(acc[0][7], w01.x, xd); fma2(acc[1][7], w01.y, xd);
            fma2(acc[2][7], w23.x, xd); fma2(acc[3][7], w23.y, xd);
        }

        if (has_next) {
            int pn = p ^ 1;
            float* wn = Ws + pn * GBK * WST;
            float* xn = Xs + pn * GBK * XST;
            #pragma unroll
            for (int i = 0; i < 8; i++) {
                int r = wr + i * 64;
                wn[(wkv*4+0)*WST + r] = wst[i].x;
                wn[(wkv*4+1)*WST + r] = wst[i].y;
                wn[(wkv*4+2)*WST + r] = wst[i].z;
                wn[(wkv*4+3)*WST + r] = wst[i].w;
            }
            if (t < 128) {
                xn[(xkv*4+0)*XST + xb] = xst.x;
                xn[(xkv*4+1)*XST + xb] = xst.y;
                xn[(xkv*4+2)*XST + xb] = xst.z;
                xn[(xkv*4+3)*XST + xb] = xst.w;
            }
        }
        __syncthreads();
        p ^= 1;
    }

    // ---- epilogue: split-K accumulate (pairs contiguous along m) ----
    #pragma unroll
    for (int mp = 0; mp < 4; mp++) {
        #pragma unroll
        for (int bj = 0; bj < 8; bj++) {
            float lo, hi;
            unpack2(acc[mp][bj], lo, hi);
            int m = m0 + ty * 8 + mp * 2;
            int b = tx * 8 + bj;
            atomicAdd(&out[(size_t)b * M + m],     lo);
            atomicAdd(&out[(size_t)b * M + m + 1], hi);
        }
    }
}

// ---------------------------------------------------------------
// Flash-decode partial: grid (NCHUNK, NUM_KV, BSZ), 256 threads.
// Token-pair processing, lazy-max online softmax in exp2 domain.
// ---------------------------------------------------------------
__global__ void __launch_bounds__(256)
attn_partial_kernel(const float* __restrict__ kvc,
                    const int*   __restrict__ seq_lens,
                    const int*   __restrict__ slot_map)
{
    int b   = blockIdx.z;
    int kvh = blockIdx.y;
    int c   = blockIdx.x;

    int seq   = seq_lens[b];
    int start = c * CHUNK;
    if (start >= seq) return;
    int end  = min(seq, start + CHUNK);
    int slot = slot_map[b];

    int lane = threadIdx.x & 31;
    int warp = threadIdx.x >> 5;

    float qr[GROUP][4];
    #pragma unroll
    for (int g = 0; g < GROUP; g++) {
        float4 q4 = *reinterpret_cast<const float4*>(
            &g_qkv[b * QKV_OUT + (kvh * GROUP + g) * HEAD_DIM + lane * 4]);
        qr[g][0] = q4.x * QSCALE; qr[g][1] = q4.y * QSCALE;
        qr[g][2] = q4.z * QSCALE; qr[g][3] = q4.w * QSCALE;
    }

    float m[GROUP], l[GROUP], o[GROUP][4];
    #pragma unroll
    for (int g = 0; g < GROUP; g++) {
        m[g] = -CUDART_INF_F; l[g] = 0.f;
        o[g][0] = o[g][1] = o[g][2] = o[g][3] = 0.f;
    }

    const size_t VPLANE = (size_t)BSZ * MAX_SEQ * NUM_KV * HEAD_DIM;
    const float* knew = &g_qkv[b * QKV_OUT + NUM_HEADS * HEAD_DIM            + kvh * HEAD_DIM];
    const float* vnew = &g_qkv[b * QKV_OUT + (NUM_HEADS + NUM_KV) * HEAD_DIM + kvh * HEAD_DIM];

    auto ldkv = [&](int s, float4& kk, float4& vv) {
        size_t base = (((size_t)b * MAX_SEQ + s) * NUM_KV + kvh) * HEAD_DIM + lane * 4;
        if (s == slot) {
            kk = *reinterpret_cast<const float4*>(knew + lane * 4);
            vv = *reinterpret_cast<const float4*>(vnew + lane * 4);
        } else {
            kk = *reinterpret_cast<const float4*>(&kvc[base]);
            vv = *reinterpret_cast<const float4*>(&kvc[VPLANE + base]);
        }
    };

    int s = start + warp;
    if (s < end) {
        float4 ka, va, kb = make_float4(0,0,0,0), vb = make_float4(0,0,0,0);
        ldkv(s, ka, va);
        bool hb = (s + 8 < end);
        if (hb) ldkv(s + 8, kb, vb);

        for (;;) {
            int sn = s + 16;
            bool hna = sn < end, hnb = sn + 8 < end;
            float4 kna, vna, knb, vnb;
            if (hna) ldkv(sn, kna, vna);
            if (hnb) ldkv(sn + 8, knb, vnb);

            float sa[GROUP], sb[GROUP];
            #pragma unroll
            for (int g = 0; g < GROUP; g++) {
                sa[g] = qr[g][0]*ka.x + qr[g][1]*ka.y + qr[g][2]*ka.z + qr[g][3]*ka.w;
                sb[g] = qr[g][0]*kb.x + qr[g][1]*kb.y + qr[g][2]*kb.z + qr[g][3]*kb.w;
            }
            #pragma unroll
            for (int off = 16; off >= 1; off >>= 1) {
                #pragma unroll
                for (int g = 0; g < GROUP; g++) {
                    sa[g] += __shfl_xor_sync(0xffffffffu, sa[g], off);
                    sb[g] += __shfl_xor_sync(0xffffffffu, sb[g], off);
                }
            }
            #pragma unroll
            for (int g = 0; g < GROUP; g++) {
                float sbe = hb ? sb[g] : -CUDART_INF_F;
                float mx  = fmaxf(sa[g], sbe);
                if (mx <= m[g]) {
                    // common path: running max unchanged, no correction
                    float pa = exp2f(sa[g] - m[g]);
                    float pb = exp2f(sbe   - m[g]);
                    l[g] += pa + pb;
                    o[g][0] += pa*va.x + pb*vb.x;
                    o[g][1] += pa*va.y + pb*vb.y;
                    o[g][2] += pa*va.z + pb*vb.z;
                    o[g][3] += pa*va.w + pb*vb.w;
                } else {
                    float corr = exp2f(m[g] - mx);   // exp2(-inf - finite) = 0: safe init
                    float pa   = exp2f(sa[g] - mx);
                    float pb   = exp2f(sbe   - mx);
                    m[g] = mx;
                    l[g] = l[g]*corr + pa + pb;
                    o[g][0] = o[g][0]*corr + pa*va.x + pb*vb.x;
                    o[g][1] = o[g][1]*corr + pa*va.y + pb*vb.y;
                    o[g][2] = o[g][2]*corr + pa*va.z + pb*vb.z;
                    o[g][3] = o[g][3]*corr + pa*va.w + pb*vb.w;
                }
            }

            if (!hna) break;
            ka = kna; va = vna; kb = knb; vb = vnb; hb = hnb; s = sn;
        }
    }

    // cross-warp merge
    __shared__ float sm_m[8][GROUP];
    __shared__ float sm_l[8][GROUP];
    __shared__ float sm_o[8][GROUP][HEAD_DIM];

    if (lane == 0) {
        #pragma unroll
        for (int g = 0; g < GROUP; g++) { sm_m[warp][g] = m[g]; sm_l[warp][g] = l[g]; }
    }
    #pragma unroll
    for (int g = 0; g < GROUP; g++) {
        sm_o[warp][g][lane*4+0] = o[g][0];
        sm_o[warp][g][lane*4+1] = o[g][1];
        sm_o[warp][g][lane*4+2] = o[g][2];
        sm_o[warp][g][lane*4+3] = o[g][3];
    }
    __syncthreads();

    if (warp < GROUP) {
        int g = warp;
        float M = -CUDART_INF_F;
        #pragma unroll
        for (int w = 0; w < 8; w++) M = fmaxf(M, sm_m[w][g]);
        float L = 0.f, O0 = 0.f, O1 = 0.f, O2 = 0.f, O3 = 0.f;
        #pragma unroll
        for (int w = 0; w < 8; w++) {
            float e = exp2f(sm_m[w][g] - M);   // empty warps: exp2(-inf - M) = 0
            L  += sm_l[w][g] * e;
            O0 += sm_o[w][g][lane*4+0] * e;
            O1 += sm_o[w][g][lane*4+1] * e;
            O2 += sm_o[w][g][lane*4+2] * e;
            O3 += sm_o[w][g][lane*4+3] * e;
        }
        size_t pidx = (((size_t)b * NUM_KV + kvh) * GROUP + g) * NCHUNK + c;
        *reinterpret_cast<float4*>(&g_po[pidx * HEAD_DIM + lane * 4]) =
            make_float4(O0, O1, O2, O3);
        if (lane == 0) { g_pml[pidx*2] = M; g_pml[pidx*2+1] = L; }
    }
}

// ---------------------------------------------------------------
__global__ void __launch_bounds__(128)
attn_reduce_kernel(const int* __restrict__ seq_lens)
{
    int h = blockIdx.x;
    int b = blockIdx.y;
    int d = threadIdx.x;
    int seq = seq_lens[b];
    int nch = (seq + CHUNK - 1) / CHUNK;
    int kvh = h >> 2, g = h & 3;

    size_t base = (((size_t)b * NUM_KV + kvh) * GROUP + g) * NCHUNK;

    float M = -CUDART_INF_F;
    for (int cc = 0; cc < nch; cc++)
        M = fmaxf(M, g_pml[(base + cc) * 2]);
    float L = 0.f, O = 0.f;
    for (int cc = 0; cc < nch; cc++) {
        float e = exp2f(g_pml[(base + cc) * 2] - M);
        L += g_pml[(base + cc) * 2 + 1] * e;
        O += g_po[(base + cc) * HEAD_DIM + d] * e;
    }
    g_attn[(size_t)b * HIDDEN + h * HEAD_DIM + d] = O / L;
}

// ---------------------------------------------------------------
extern "C" void kernel_launch(void* const* d_in, const int* in_sizes, int n_in,
                              void* d_out, int out_size)
{
    const float* hidden = (const float*)d_in[0];
    const float* kvc    = (const float*)d_in[2];
    const int*   slot   = (const int*)  d_in[3];
    const int*   seql   = (const int*)  d_in[4];
    const float* Wqkv   = (const float*)d_in[5];
    const float* bqkv   = (const float*)d_in[6];
    const float* Wo     = (const float*)d_in[7];
    float*       out    = (float*)d_out;

    void *pq = nullptr, *pa = nullptr;
    cudaGetSymbolAddress(&pq, g_qkv);
    cudaGetSymbolAddress(&pa, g_attn);
    float* qkv  = (float*)pq;
    float* attn = (float*)pa;

    cudaFuncSetAttribute(gemm8x8_kernel,
                         cudaFuncAttributeMaxDynamicSharedMemorySize, GSMEM);

    // init outputs (bias for qkv, zeros for out)
    init_bias_kernel<<<(BSZ * QKV_OUT + 255) / 256, 256>>>(qkv, bqkv, QKV_OUT);
    init_bias_kernel<<<(BSZ * HIDDEN + 255) / 256, 256>>>(out, nullptr, HIDDEN);

    // 1) QKV projection: 12 m-blocks x 12 splits = 144 blocks (one wave)
    gemm8x8_kernel<<<dim3(QKV_OUT / GBM, 12), 256, GSMEM>>>(Wqkv, hidden, qkv, QKV_OUT, HIDDEN, 12);

    // 2) flash-decode partials
    attn_partial_kernel<<<dim3(NCHUNK, NUM_KV, BSZ), 256>>>(kvc, seql, slot);

    // 3) merge partials
    attn_reduce_kernel<<<dim3(NUM_HEADS, BSZ), 128>>>(seql);

    // 4) output projection: 8 m-blocks x 18 splits = 144 blocks
    gemm8x8_kernel<<<dim3(HIDDEN / GBM, 18), 256, GSMEM>>>(Wo, attn, out, HIDDEN, HIDDEN, 18);
}

// round 4
// speedup vs baseline: 3.1140x; 1.1356x over previous
#include <cuda_runtime.h>
#include <math_constants.h>

#define NUM_HEADS 32
#define NUM_KV    8
#define HEAD_DIM  128
#define HIDDEN    4096
#define BSZ       32
#define MAX_SEQ   4096
#define GROUP     4
#define QKV_OUT   6144
#define CHUNK     128
#define NCHUNK    32
// attention scale * log2(e): softmax in exp2 domain
#define QSCALE    (0.08838834764831845f * 1.4426950408889634f)

// GEMM tiling: BM=512, BK=8, 256 threads, per-thread 8m x 8b
#define GBM 512
#define GBK 8
#define WST 516
#define XST 36
#define QKV_SPLIT 24     // 12 m-blocks x 24 = 288 blocks
#define WO_SPLIT  36     // 8 m-blocks x 36 = 288 blocks

// ---------------- scratch (no allocs allowed) ----------------
__device__ float g_qkv [BSZ * QKV_OUT];
__device__ float g_attn[BSZ * NUM_HEADS * HEAD_DIM];
__device__ float g_part[QKV_SPLIT * BSZ * QKV_OUT];            // 18.9 MB (= WO_SPLIT*BSZ*HIDDEN)
__device__ float g_po  [BSZ * NUM_KV * GROUP * NCHUNK * HEAD_DIM];
__device__ float g_pml [BSZ * NUM_KV * GROUP * NCHUNK * 2];

// packed fp32x2 FMA (Blackwell)
__device__ __forceinline__ void fma2(unsigned long long& d,
                                     unsigned long long a,
                                     unsigned long long b) {
    asm("fma.rn.f32x2 %0, %1, %2, %0;" : "+l"(d) : "l"(a), "l"(b));
}
__device__ __forceinline__ unsigned long long dup2(float v) {
    unsigned long long r;
    asm("mov.b64 %0, {%1, %1};" : "=l"(r) : "f"(v));
    return r;
}

// ---------------------------------------------------------------
// Split-K GEMM writing per-split partials (no atomics).
// part[split][b][m] = sum_{k in split} x[b,k]*W[m,k]
// ---------------------------------------------------------------
__global__ void __launch_bounds__(256, 2)
gemm8x8_kernel(const float* __restrict__ W, const float* __restrict__ x,
               float* __restrict__ part, int M, int K, int nsplit)
{
    __shared__ __align__(16) float Ws[2][GBK][WST];
    __shared__ __align__(16) float Xs[2][GBK][XST];

    const int m0    = blockIdx.x * GBM;
    const int tot   = K / GBK;
    const int tile0 = (blockIdx.y * tot) / nsplit;
    const int tile1 = ((blockIdx.y + 1) * tot) / nsplit;

    const int t   = threadIdx.x;
    const int ty  = t >> 2;     // 0..63  -> 8 m rows
    const int tx  = t & 3;      // 0..3   -> 8 batches
    const int r0  = t >> 1;     // W load base row
    const int wkv = t & 1;      // which float4 of the 8-k chunk
    const int xb  = t & 31;     // x load batch (t<64)
    const int xkv = t >> 5;

    float4 wst[4];
    float4 xst;

    // ---- prologue ----
    {
        const float* wp = W + (size_t)(m0 + r0) * K + (size_t)tile0 * GBK + wkv * 4;
        #pragma unroll
        for (int i = 0; i < 4; i++)
            wst[i] = *reinterpret_cast<const float4*>(wp + (size_t)i * 128 * K);
        if (t < 64)
            xst = *reinterpret_cast<const float4*>(x + (size_t)xb * K + (size_t)tile0 * GBK + xkv * 4);

        #pragma unroll
        for (int i = 0; i < 4; i++) {
            int r = r0 + i * 128;
            Ws[0][wkv*4+0][r] = wst[i].x;
            Ws[0][wkv*4+1][r] = wst[i].y;
            Ws[0][wkv*4+2][r] = wst[i].z;
            Ws[0][wkv*4+3][r] = wst[i].w;
        }
        if (t < 64) {
            Xs[0][xkv*4+0][xb] = xst.x;
            Xs[0][xkv*4+1][xb] = xst.y;
            Xs[0][xkv*4+2][xb] = xst.z;
            Xs[0][xkv*4+3][xb] = xst.w;
        }
    }
    __syncthreads();

    unsigned long long acc[4][8];
    #pragma unroll
    for (int i = 0; i < 4; i++)
        #pragma unroll
        for (int j = 0; j < 8; j++) acc[i][j] = 0ull;

    int p = 0;
    for (int tile = tile0; tile < tile1; tile++) {
        const bool has_next = (tile + 1 < tile1);
        if (has_next) {
            const float* wp = W + (size_t)(m0 + r0) * K + (size_t)(tile + 1) * GBK + wkv * 4;
            #pragma unroll
            for (int i = 0; i < 4; i++)
                wst[i] = *reinterpret_cast<const float4*>(wp + (size_t)i * 128 * K);
            if (t < 64)
                xst = *reinterpret_cast<const float4*>(x + (size_t)xb * K + (size_t)(tile + 1) * GBK + xkv * 4);
        }

        #pragma unroll
        for (int k = 0; k < GBK; k++) {
            ulonglong2 w01 = *reinterpret_cast<const ulonglong2*>(&Ws[p][k][ty * 8]);
            ulonglong2 w23 = *reinterpret_cast<const ulonglong2*>(&Ws[p][k][ty * 8 + 4]);
            float4 xa = *reinterpret_cast<const float4*>(&Xs[p][k][tx * 8]);
            float4 xc = *reinterpret_cast<const float4*>(&Xs[p][k][tx * 8 + 4]);
            unsigned long long xd;
            xd = dup2(xa.x);
            fma2(acc[0][0], w01.x, xd); fma2(acc[1][0], w01.y, xd);
            fma2(acc[2][0], w23.x, xd); fma2(acc[3][0], w23.y, xd);
            xd = dup2(xa.y);
            fma2(acc[0][1], w01.x, xd); fma2(acc[1][1], w01.y, xd);
            fma2(acc[2][1], w23.x, xd); fma2(acc[3][1], w23.y, xd);
            xd = dup2(xa.z);
            fma2(acc[0][2], w01.x, xd); fma2(acc[1][2], w01.y, xd);
            fma2(acc[2][2], w23.x, xd); fma2(acc[3][2], w23.y, xd);
            xd = dup2(xa.w);
            fma2(acc[0][3], w01.x, xd); fma2(acc[1][3], w01.y, xd);
            fma2(acc[2][3], w23.x, xd); fma2(acc[3][3], w23.y, xd);
            xd = dup2(xc.x);
            fma2(acc[0][4], w01.x, xd); fma2(acc[1][4], w01.y, xd);
            fma2(acc[2][4], w23.x, xd); fma2(acc[3][4], w23.y, xd);
            xd = dup2(xc.y);
            fma2(acc[0][5], w01.x, xd); fma2(acc[1][5], w01.y, xd);
            fma2(acc[2][5], w23.x, xd); fma2(acc[3][5], w23.y, xd);
            xd = dup2(xc.z);
            fma2(acc[0][6], w01.x, xd); fma2(acc[1][6], w01.y, xd);
            fma2(acc[2][6], w23.x, xd); fma2(acc[3][6], w23.y, xd);
            xd = dup2(xc.w);
            fma2(acc[0][7], w01.x, xd); fma2(acc[1][7], w01.y, xd);
            fma2(acc[2][7], w23.x, xd); fma2(acc[3][7], w23.y, xd);
        }

        if (has_next) {
            int pn = p ^ 1;
            #pragma unroll
            for (int i = 0; i < 4; i++) {
                int r = r0 + i * 128;
                Ws[pn][wkv*4+0][r] = wst[i].x;
                Ws[pn][wkv*4+1][r] = wst[i].y;
                Ws[pn][wkv*4+2][r] = wst[i].z;
                Ws[pn][wkv*4+3][r] = wst[i].w;
            }
            if (t < 64) {
                Xs[pn][xkv*4+0][xb] = xst.x;
                Xs[pn][xkv*4+1][xb] = xst.y;
                Xs[pn][xkv*4+2][xb] = xst.z;
                Xs[pn][xkv*4+3][xb] = xst.w;
            }
        }
        __syncthreads();
        p ^= 1;
    }

    // ---- epilogue: plain vector stores of partials ----
    float* pp = part + (size_t)blockIdx.y * BSZ * M;
    #pragma unroll
    for (int bj = 0; bj < 8; bj++) {
        int b = tx * 8 + bj;
        float* dst = pp + (size_t)b * M + m0 + ty * 8;
        ulonglong2 lo = make_ulonglong2(acc[0][bj], acc[1][bj]);
        ulonglong2 hi = make_ulonglong2(acc[2][bj], acc[3][bj]);
        *reinterpret_cast<ulonglong2*>(dst)     = lo;
        *reinterpret_cast<ulonglong2*>(dst + 4) = hi;
    }
}

// ---------------------------------------------------------------
// reduce partials: out[b,m] = bias[m] + sum_s part[s,b,m]  (float4 wide)
// ---------------------------------------------------------------
__global__ void __launch_bounds__(256)
reduce_part_kernel(const float4* __restrict__ part, const float4* __restrict__ bias,
                   float4* __restrict__ out, int M4, int nsplit)
{
    int idx = blockIdx.x * 256 + threadIdx.x;
    if (idx >= BSZ * M4) return;
    float4 a = bias ? bias[idx % M4] : make_float4(0.f, 0.f, 0.f, 0.f);
    for (int s = 0; s < nsplit; s++) {
        float4 pv = part[(size_t)s * BSZ * M4 + idx];
        a.x += pv.x; a.y += pv.y; a.z += pv.z; a.w += pv.w;
    }
    out[idx] = a;
}

// ---------------------------------------------------------------
// Flash-decode partial: grid (NCHUNK, NUM_KV, BSZ), 128 threads (4 warps).
// 4-token batches, full next-batch prefetch (8 LDG.128 in flight / warp),
// lazy-max online softmax in exp2 domain (warp-uniform branch).
// ---------------------------------------------------------------
__global__ void __launch_bounds__(128, 4)
attn_partial_kernel(const float* __restrict__ kvc,
                    const int*   __restrict__ seq_lens,
                    const int*   __restrict__ slot_map)
{
    int b   = blockIdx.z;
    int kvh = blockIdx.y;
    int c   = blockIdx.x;

    int seq   = seq_lens[b];
    int start = c * CHUNK;
    if (start >= seq) return;
    int end  = min(seq, start + CHUNK);
    int slot = slot_map[b];

    int lane = threadIdx.x & 31;
    int warp = threadIdx.x >> 5;   // 0..3

    float qr[GROUP][4];
    #pragma unroll
    for (int g = 0; g < GROUP; g++) {
        float4 q4 = *reinterpret_cast<const float4*>(
            &g_qkv[b * QKV_OUT + (kvh * GROUP + g) * HEAD_DIM + lane * 4]);
        qr[g][0] = q4.x * QSCALE; qr[g][1] = q4.y * QSCALE;
        qr[g][2] = q4.z * QSCALE; qr[g][3] = q4.w * QSCALE;
    }

    float m[GROUP], l[GROUP], o[GROUP][4];
    #pragma unroll
    for (int g = 0; g < GROUP; g++) {
        m[g] = -CUDART_INF_F; l[g] = 0.f;
        o[g][0] = o[g][1] = o[g][2] = o[g][3] = 0.f;
    }

    const size_t VPLANE = (size_t)BSZ * MAX_SEQ * NUM_KV * HEAD_DIM;
    const float* knew = &g_qkv[b * QKV_OUT + NUM_HEADS * HEAD_DIM            + kvh * HEAD_DIM];
    const float* vnew = &g_qkv[b * QKV_OUT + (NUM_HEADS + NUM_KV) * HEAD_DIM + kvh * HEAD_DIM];

    auto ldkv = [&](int s, float4& kk, float4& vv) {
        size_t base = (((size_t)b * MAX_SEQ + s) * NUM_KV + kvh) * HEAD_DIM + lane * 4;
        if (s == slot) {
            kk = *reinterpret_cast<const float4*>(knew + lane * 4);
            vv = *reinterpret_cast<const float4*>(vnew + lane * 4);
        } else {
            kk = *reinterpret_cast<const float4*>(&kvc[base]);
            vv = *reinterpret_cast<const float4*>(&kvc[VPLANE + base]);
        }
    };

    int s = start + warp * 4;
    if (s < end) {
        float4 kc[4], vc[4];
        #pragma unroll
        for (int j = 0; j < 4; j++) { kc[j] = make_float4(0,0,0,0); vc[j] = kc[j]; }
        #pragma unroll
        for (int j = 0; j < 4; j++)
            if (s + j < end) ldkv(s + j, kc[j], vc[j]);

        for (;;) {
            int sn = s + 16;
            bool more = (sn < end);
            float4 kn[4], vn[4];
            if (more) {
                #pragma unroll
                for (int j = 0; j < 4; j++)
                    if (sn + j < end) ldkv(sn + j, kn[j], vn[j]);
            }

            // scores for 4 tokens x 4 groups
            float sc[4][GROUP];
            #pragma unroll
            for (int j = 0; j < 4; j++) {
                #pragma unroll
                for (int g = 0; g < GROUP; g++)
                    sc[j][g] = qr[g][0]*kc[j].x + qr[g][1]*kc[j].y
                             + qr[g][2]*kc[j].z + qr[g][3]*kc[j].w;
            }
            #pragma unroll
            for (int off = 16; off >= 1; off >>= 1) {
                #pragma unroll
                for (int j = 0; j < 4; j++)
                    #pragma unroll
                    for (int g = 0; g < GROUP; g++)
                        sc[j][g] += __shfl_xor_sync(0xffffffffu, sc[j][g], off);
            }
            #pragma unroll
            for (int j = 1; j < 4; j++) {
                if (s + j >= end) {
                    #pragma unroll
                    for (int g = 0; g < GROUP; g++) sc[j][g] = -CUDART_INF_F;
                }
            }

            #pragma unroll
            for (int g = 0; g < GROUP; g++) {
                float mx = fmaxf(fmaxf(sc[0][g], sc[1][g]), fmaxf(sc[2][g], sc[3][g]));
                float p0, p1, p2, p3;
                if (mx <= m[g]) {
                    p0 = exp2f(sc[0][g] - m[g]); p1 = exp2f(sc[1][g] - m[g]);
                    p2 = exp2f(sc[2][g] - m[g]); p3 = exp2f(sc[3][g] - m[g]);
                    l[g] += (p0 + p1) + (p2 + p3);
                } else {
                    float corr = exp2f(m[g] - mx);   // exp2(-inf - finite) = 0: safe
                    m[g] = mx;
                    p0 = exp2f(sc[0][g] - mx); p1 = exp2f(sc[1][g] - mx);
                    p2 = exp2f(sc[2][g] - mx); p3 = exp2f(sc[3][g] - mx);
                    l[g] = l[g] * corr + (p0 + p1) + (p2 + p3);
                    o[g][0] *= corr; o[g][1] *= corr; o[g][2] *= corr; o[g][3] *= corr;
                }
                o[g][0] += p0*vc[0].x + p1*vc[1].x + p2*vc[2].x + p3*vc[3].x;
                o[g][1] += p0*vc[0].y + p1*vc[1].y + p2*vc[2].y + p3*vc[3].y;
                o[g][2] += p0*vc[0].z + p1*vc[1].z + p2*vc[2].z + p3*vc[3].z;
                o[g][3] += p0*vc[0].w + p1*vc[1].w + p2*vc[2].w + p3*vc[3].w;
            }

            if (!more) break;
            #pragma unroll
            for (int j = 0; j < 4; j++) { kc[j] = kn[j]; vc[j] = vn[j]; }
            s = sn;
        }
    }

    // cross-warp merge (4 warps)
    __shared__ float sm_m[4][GROUP];
    __shared__ float sm_l[4][GROUP];
    __shared__ float sm_o[4][GROUP][HEAD_DIM];

    if (lane == 0) {
        #pragma unroll
        for (int g = 0; g < GROUP; g++) { sm_m[warp][g] = m[g]; sm_l[warp][g] = l[g]; }
    }
    #pragma unroll
    for (int g = 0; g < GROUP; g++) {
        sm_o[warp][g][lane*4+0] = o[g][0];
        sm_o[warp][g][lane*4+1] = o[g][1];
        sm_o[warp][g][lane*4+2] = o[g][2];
        sm_o[warp][g][lane*4+3] = o[g][3];
    }
    __syncthreads();

    {
        int g = warp;   // GROUP == 4 warps
        float M = -CUDART_INF_F;
        #pragma unroll
        for (int w = 0; w < 4; w++) M = fmaxf(M, sm_m[w][g]);
        float L = 0.f, O0 = 0.f, O1 = 0.f, O2 = 0.f, O3 = 0.f;
        #pragma unroll
        for (int w = 0; w < 4; w++) {
            float e = exp2f(sm_m[w][g] - M);   // empty warps contribute 0
            L  += sm_l[w][g] * e;
            O0 += sm_o[w][g][lane*4+0] * e;
            O1 += sm_o[w][g][lane*4+1] * e;
            O2 += sm_o[w][g][lane*4+2] * e;
            O3 += sm_o[w][g][lane*4+3] * e;
        }
        size_t pidx = (((size_t)b * NUM_KV + kvh) * GROUP + g) * NCHUNK + c;
        *reinterpret_cast<float4*>(&g_po[pidx * HEAD_DIM + lane * 4]) =
            make_float4(O0, O1, O2, O3);
        if (lane == 0) { g_pml[pidx*2] = M; g_pml[pidx*2+1] = L; }
    }
}

// ---------------------------------------------------------------
__global__ void __launch_bounds__(128)
attn_reduce_kernel(const int* __restrict__ seq_lens)
{
    int h = blockIdx.x;
    int b = blockIdx.y;
    int d = threadIdx.x;
    int seq = seq_lens[b];
    int nch = (seq + CHUNK - 1) / CHUNK;
    int kvh = h >> 2, g = h & 3;

    size_t base = (((size_t)b * NUM_KV + kvh) * GROUP + g) * NCHUNK;

    float M = -CUDART_INF_F;
    for (int cc = 0; cc < nch; cc++)
        M = fmaxf(M, g_pml[(base + cc) * 2]);
    float L = 0.f, O = 0.f;
    for (int cc = 0; cc < nch; cc++) {
        float e = exp2f(g_pml[(base + cc) * 2] - M);
        L += g_pml[(base + cc) * 2 + 1] * e;
        O += g_po[(base + cc) * HEAD_DIM + d] * e;
    }
    g_attn[(size_t)b * HIDDEN + h * HEAD_DIM + d] = O / L;
}

// ---------------------------------------------------------------
extern "C" void kernel_launch(void* const* d_in, const int* in_sizes, int n_in,
                              void* d_out, int out_size)
{
    const float* hidden = (const float*)d_in[0];
    const float* kvc    = (const float*)d_in[2];
    const int*   slot   = (const int*)  d_in[3];
    const int*   seql   = (const int*)  d_in[4];
    const float* Wqkv   = (const float*)d_in[5];
    const float* bqkv   = (const float*)d_in[6];
    const float* Wo     = (const float*)d_in[7];
    float*       out    = (float*)d_out;

    void *pq = nullptr, *pa = nullptr, *pp = nullptr;
    cudaGetSymbolAddress(&pq, g_qkv);
    cudaGetSymbolAddress(&pa, g_attn);
    cudaGetSymbolAddress(&pp, g_part);
    float* qkv  = (float*)pq;
    float* attn = (float*)pa;
    float* part = (float*)pp;

    // 1) QKV projection: partials + reduce (bias folded into reduce)
    gemm8x8_kernel<<<dim3(QKV_OUT / GBM, QKV_SPLIT), 256>>>(Wqkv, hidden, part, QKV_OUT, HIDDEN, QKV_SPLIT);
    reduce_part_kernel<<<(BSZ * QKV_OUT / 4 + 255) / 256, 256>>>(
        (const float4*)part, (const float4*)bqkv, (float4*)qkv, QKV_OUT / 4, QKV_SPLIT);

    // 2) flash-decode partials
    attn_partial_kernel<<<dim3(NCHUNK, NUM_KV, BSZ), 128>>>(kvc, seql, slot);

    // 3) merge partials
    attn_reduce_kernel<<<dim3(NUM_HEADS, BSZ), 128>>>(seql);

    // 4) output projection: partials + reduce (writes d_out directly)
    gemm8x8_kernel<<<dim3(HIDDEN / GBM, WO_SPLIT), 256>>>(Wo, attn, part, HIDDEN, HIDDEN, WO_SPLIT);
    reduce_part_kernel<<<(BSZ * HIDDEN / 4 + 255) / 256, 256>>>(
        (const float4*)part, nullptr, (float4*)out, HIDDEN / 4, WO_SPLIT);
}